// round 3
// baseline (speedup 1.0000x reference)
#include <cuda_runtime.h>
#include <math.h>

#define N_NODES 8192
#define D 64
#define NT 8192

// Scratch (no allocations allowed)
__device__ float g_deg[N_NODES];
__device__ float g_dinv[N_NODES];
__device__ float g_h[N_NODES * D];    // x @ W
__device__ float g_agg[N_NODES * D];  // aggregated + relu (in place)

// Resolved input pointers (metadata order/dtype untrusted -> classify at runtime)
__device__ const float* gp_x;
__device__ const void*  gp_ei;
__device__ const float* gp_W;
__device__ const float* gp_b;
__device__ int          g_E;
__device__ int          g_ei32;   // 1 if edge indices are int32, 0 if int64

__device__ __forceinline__ int fetch_idx(int i, int ei32) {
    if (ei32) return ((const int*)gp_ei)[i];
    return (int)((const long long*)gp_ei)[i];
}

// ---------------- classify inputs by size + content ----------------
__device__ bool range_ok_i64(const long long* p, int n) {
    int stride = n / 64; if (stride < 1) stride = 1;
    for (int k = 0; k < 64; k++) {
        long long v = p[(long long)k * stride];
        if (v < 0 || v >= N_NODES) return false;
    }
    return true;
}
__device__ bool range_ok_i32(const int* p, int n) {
    int stride = n / 64; if (stride < 1) stride = 1;
    for (int k = 0; k < 64; k++) {
        int v = p[k * stride];
        if (v < 0 || v >= N_NODES) return false;
    }
    return true;
}

__global__ void k_classify(const void* p0, const void* p1, const void* p2, const void* p3,
                           int s0, int s1, int s2, int s3) {
    if (threadIdx.x != 0 || blockIdx.x != 0) return;
    const void* ps[4] = {p0, p1, p2, p3};
    int ss[4] = {s0, s1, s2, s3};
    int big[2]; int nb = 0;
    for (int i = 0; i < 4; i++) {
        if (ss[i] == D) gp_b = (const float*)ps[i];
        else if (ss[i] == D * D) gp_W = (const float*)ps[i];
        else if (nb < 2) big[nb++] = i;
    }
    // Try each (buffer, index-width) interpretation; exactly one should pass.
    for (int c = 0; c < 2; c++) {
        const void* cand = ps[big[c]];
        int n = ss[big[c]];
        const void* other = ps[big[1 - c]];
        // int64 interpretation: n elements of int64 (if that's the true dtype,
        // element count n covers the full buffer)
        if (range_ok_i64((const long long*)cand, n)) {
            gp_ei = cand; g_ei32 = 0; g_E = n / 2;
            gp_x = (const float*)other;
            return;
        }
        if (range_ok_i32((const int*)cand, n)) {
            gp_ei = cand; g_ei32 = 1; g_E = n / 2;
            gp_x = (const float*)other;
            return;
        }
    }
    // Fallback (should not happen): assume big[1] is edges, int32
    gp_ei = ps[big[1]]; g_ei32 = 1; g_E = ss[big[1]] / 2;
    gp_x = (const float*)ps[big[0]];
}

// ---------------- degree ----------------
__global__ void k_deg_init() {
    int i = blockIdx.x * blockDim.x + threadIdx.x;
    if (i < N_NODES) g_deg[i] = 1.0f;  // self-loop
}

__global__ void k_deg_count(int Emax) {
    int e = blockIdx.x * blockDim.x + threadIdx.x;
    int E = g_E;
    int ei32 = g_ei32;
    if (e < E && e < Emax) {
        int dst = fetch_idx(E + e, ei32);
        if ((unsigned)dst < (unsigned)N_NODES)
            atomicAdd(&g_deg[dst], 1.0f);
    }
}

__global__ void k_dinv() {
    int i = blockIdx.x * blockDim.x + threadIdx.x;
    if (i < N_NODES) g_dinv[i] = 1.0f / sqrtf(g_deg[i]);  // deg >= 1 always
}

// ---------------- h = x @ W ----------------
__global__ void k_xw() {
    __shared__ float sW[D * D];
    const float* __restrict__ x = gp_x;
    const float* __restrict__ W = gp_W;
    int tid = threadIdx.x;
    for (int i = tid; i < D * D; i += 256) sW[i] = W[i];
    __syncthreads();
    int row = blockIdx.x * 4 + (tid >> 6);
    int col = tid & 63;
    const float* xr = x + row * D;
    float acc = 0.0f;
#pragma unroll
    for (int k = 0; k < D; k++) acc += xr[k] * sW[k * D + col];
    g_h[row * D + col] = acc;
}

// ---------------- agg init with self-loop term ----------------
__global__ void k_agg_init() {
    int idx = blockIdx.x * blockDim.x + threadIdx.x;
    if (idx < N_NODES * D) {
        int i = idx >> 6;  // /D
        float di = g_dinv[i];
        g_agg[idx] = di * di * g_h[idx];
    }
}

// ---------------- edge scatter: warp per edge ----------------
__global__ void k_scatter(int Emax) {
    int gw = (blockIdx.x * blockDim.x + threadIdx.x) >> 5;
    int lane = threadIdx.x & 31;
    int E = g_E;
    int ei32 = g_ei32;
    if (gw >= E || gw >= Emax) return;
    int src = fetch_idx(gw, ei32);
    int dst = fetch_idx(E + gw, ei32);
    if ((unsigned)src >= (unsigned)N_NODES) return;
    if ((unsigned)dst >= (unsigned)N_NODES) return;
    float norm = g_dinv[src] * g_dinv[dst];
    float2 v = ((const float2*)(g_h + src * D))[lane];
    atomicAdd(&g_agg[dst * D + lane * 2],     norm * v.x);
    atomicAdd(&g_agg[dst * D + lane * 2 + 1], norm * v.y);
}

// ---------------- bias + relu (in place) ----------------
__global__ void k_bias_relu() {
    const float* __restrict__ b = gp_b;
    int idx = blockIdx.x * blockDim.x + threadIdx.x;
    if (idx < N_NODES * D) {
        float v = g_agg[idx] + b[idx & 63];
        g_agg[idx] = v > 0.0f ? v : 0.0f;
    }
}

// ---------------- C = H @ H^T, fp32 SIMT, 128x128 tile ----------------
__global__ void __launch_bounds__(256, 2) k_gemm(float* __restrict__ C) {
    __shared__ float As[32][132];
    __shared__ float Bs[32][132];

    int tid = threadIdx.x;
    int bi = blockIdx.y, bj = blockIdx.x;
    const float* A = g_agg + bi * 128 * D;
    const float* B = g_agg + bj * 128 * D;

    int tx = tid & 15, ty = tid >> 4;
    float acc[8][8];
#pragma unroll
    for (int ii = 0; ii < 8; ii++)
#pragma unroll
        for (int jj = 0; jj < 8; jj++) acc[ii][jj] = 0.0f;

#pragma unroll
    for (int kt = 0; kt < 2; kt++) {
#pragma unroll
        for (int it = 0; it < 4; it++) {
            int q = tid + it * 256;      // 0..1023
            int i = q >> 3;              // row 0..127
            int k4 = q & 7;              // float4 index within 32-col chunk
            float4 a = ((const float4*)(A + i * D + kt * 32))[k4];
            float4 bb = ((const float4*)(B + i * D + kt * 32))[k4];
            int k = k4 * 4;
            As[k][i] = a.x; As[k + 1][i] = a.y; As[k + 2][i] = a.z; As[k + 3][i] = a.w;
            Bs[k][i] = bb.x; Bs[k + 1][i] = bb.y; Bs[k + 2][i] = bb.z; Bs[k + 3][i] = bb.w;
        }
        __syncthreads();

#pragma unroll
        for (int k = 0; k < 32; k++) {
            float a[8], b[8];
            *(float4*)(a)     = *(const float4*)&As[k][ty * 8];
            *(float4*)(a + 4) = *(const float4*)&As[k][ty * 8 + 4];
            *(float4*)(b)     = *(const float4*)&Bs[k][tx * 8];
            *(float4*)(b + 4) = *(const float4*)&Bs[k][tx * 8 + 4];
#pragma unroll
            for (int ii = 0; ii < 8; ii++)
#pragma unroll
                for (int jj = 0; jj < 8; jj++)
                    acc[ii][jj] = fmaf(a[ii], b[jj], acc[ii][jj]);
        }
        __syncthreads();
    }

#pragma unroll
    for (int ii = 0; ii < 8; ii++) {
        int row = bi * 128 + ty * 8 + ii;
        float* cp = C + (long long)row * NT + bj * 128 + tx * 8;
        float4 v0 = make_float4(acc[ii][0], acc[ii][1], acc[ii][2], acc[ii][3]);
        float4 v1 = make_float4(acc[ii][4], acc[ii][5], acc[ii][6], acc[ii][7]);
        ((float4*)cp)[0] = v0;
        ((float4*)cp)[1] = v1;
    }
}

extern "C" void kernel_launch(void* const* d_in, const int* in_sizes, int n_in,
                              void* d_out, int out_size) {
    float* out = (float*)d_out;

    const void* p0 = n_in > 0 ? d_in[0] : nullptr;
    const void* p1 = n_in > 1 ? d_in[1] : nullptr;
    const void* p2 = n_in > 2 ? d_in[2] : nullptr;
    const void* p3 = n_in > 3 ? d_in[3] : nullptr;
    int s0 = n_in > 0 ? in_sizes[0] : 0;
    int s1 = n_in > 1 ? in_sizes[1] : 0;
    int s2 = n_in > 2 ? in_sizes[2] : 0;
    int s3 = n_in > 3 ? in_sizes[3] : 0;

    int Emax = 0;
    for (int i = 0; i < n_in && i < 4; i++) {
        int s = in_sizes[i];
        if (s != D && s != D * D && s / 2 > Emax) Emax = s / 2;
    }

    k_classify<<<1, 32>>>(p0, p1, p2, p3, s0, s1, s2, s3);
    k_deg_init<<<(N_NODES + 255) / 256, 256>>>();
    k_deg_count<<<(Emax + 255) / 256, 256>>>(Emax);
    k_dinv<<<(N_NODES + 255) / 256, 256>>>();
    k_xw<<<N_NODES / 4, 256>>>();
    k_agg_init<<<(N_NODES * D + 255) / 256, 256>>>();
    k_scatter<<<(Emax + 7) / 8, 256>>>(Emax);
    k_bias_relu<<<(N_NODES * D + 255) / 256, 256>>>();

    dim3 grid(NT / 128, NT / 128);
    k_gemm<<<grid, 256>>>(out);
}

// round 5
// speedup vs baseline: 1.6164x; 1.6164x over previous
#include <cuda_runtime.h>
#include <cuda_bf16.h>
#include <math.h>
#include <stdint.h>

#define N_NODES 8192
#define D 64
#define NT 8192
#define KC 192            // packed K: [hi | lo | hi] / [hi | hi | lo]

// ---------------- scratch (no allocations allowed) ----------------
__device__ float g_deg[N_NODES];
__device__ float g_h[N_NODES * D];     // x @ W
__device__ float g_agg[N_NODES * D];   // aggregated
__device__ __nv_bfloat16 g_A2[N_NODES * KC];
__device__ __nv_bfloat16 g_B2[N_NODES * KC];

// Resolved input pointers (metadata order/dtype untrusted -> classify at runtime)
__device__ const float* gp_x;
__device__ const void*  gp_ei;
__device__ const float* gp_W;
__device__ const float* gp_b;
__device__ int          g_E;
__device__ int          g_ei32;   // 1 if edge indices are int32, 0 if int64

__device__ __forceinline__ int fetch_idx(int i, int ei32) {
    if (ei32) return ((const int*)gp_ei)[i];
    return (int)((const long long*)gp_ei)[i];
}

__device__ __forceinline__ uint32_t smem_u32(const void* p) {
    uint32_t a;
    asm("{ .reg .u64 t; cvta.to.shared.u64 t, %1; cvt.u32.u64 %0, t; }" : "=r"(a) : "l"(p));
    return a;
}

// ---------------- classify (thread 0) + deg init (all) ----------------
__device__ bool range_ok_i64(const long long* p, int n) {
    int stride = n / 64; if (stride < 1) stride = 1;
    for (int k = 0; k < 64; k++) {
        long long v = p[(long long)k * stride];
        if (v < 0 || v >= N_NODES) return false;
    }
    return true;
}
__device__ bool range_ok_i32(const int* p, int n) {
    int stride = n / 64; if (stride < 1) stride = 1;
    for (int k = 0; k < 64; k++) {
        int v = p[k * stride];
        if (v < 0 || v >= N_NODES) return false;
    }
    return true;
}

__global__ void k_classify_deginit(const void* p0, const void* p1, const void* p2, const void* p3,
                                   int s0, int s1, int s2, int s3) {
    int i = blockIdx.x * blockDim.x + threadIdx.x;
    if (i < N_NODES) g_deg[i] = 1.0f;  // self-loop
    if (i != 0) return;

    const void* ps[4] = {p0, p1, p2, p3};
    int ss[4] = {s0, s1, s2, s3};
    int big[2]; int nb = 0;
    for (int j = 0; j < 4; j++) {
        if (ss[j] == D) gp_b = (const float*)ps[j];
        else if (ss[j] == D * D) gp_W = (const float*)ps[j];
        else if (nb < 2) big[nb++] = j;
    }
    for (int c = 0; c < 2; c++) {
        const void* cand = ps[big[c]];
        int n = ss[big[c]];
        const void* other = ps[big[1 - c]];
        if (range_ok_i64((const long long*)cand, n)) {
            gp_ei = cand; g_ei32 = 0; g_E = n / 2; gp_x = (const float*)other; return;
        }
        if (range_ok_i32((const int*)cand, n)) {
            gp_ei = cand; g_ei32 = 1; g_E = n / 2; gp_x = (const float*)other; return;
        }
    }
    gp_ei = ps[big[1]]; g_ei32 = 1; g_E = ss[big[1]] / 2;
    gp_x = (const float*)ps[big[0]];
}

__global__ void k_deg_count(int Emax) {
    int e = blockIdx.x * blockDim.x + threadIdx.x;
    int E = g_E, ei32 = g_ei32;
    if (e < E && e < Emax) {
        int dst = fetch_idx(E + e, ei32);
        if ((unsigned)dst < (unsigned)N_NODES) atomicAdd(&g_deg[dst], 1.0f);
    }
}

// ---------------- h = x @ W ----------------
__global__ void k_xw() {
    __shared__ float sW[D * D];
    const float* __restrict__ x = gp_x;
    const float* __restrict__ W = gp_W;
    int tid = threadIdx.x;
    for (int i = tid; i < D * D; i += 256) sW[i] = W[i];
    __syncthreads();
    int row = blockIdx.x * 4 + (tid >> 6);
    int col = tid & 63;
    const float* xr = x + row * D;
    float acc = 0.0f;
#pragma unroll
    for (int k = 0; k < D; k++) acc += xr[k] * sW[k * D + col];
    g_h[row * D + col] = acc;
}

// ---------------- agg init with self-loop term (1/deg) ----------------
__global__ void k_agg_init() {
    int idx = blockIdx.x * blockDim.x + threadIdx.x;
    if (idx < N_NODES * D) {
        int i = idx >> 6;
        float di = rsqrtf(g_deg[i]);
        g_agg[idx] = di * di * g_h[idx];
    }
}

// ---------------- edge scatter: warp per edge ----------------
__global__ void k_scatter(int Emax) {
    int gw = (blockIdx.x * blockDim.x + threadIdx.x) >> 5;
    int lane = threadIdx.x & 31;
    int E = g_E, ei32 = g_ei32;
    if (gw >= E || gw >= Emax) return;
    int src = fetch_idx(gw, ei32);
    int dst = fetch_idx(E + gw, ei32);
    if ((unsigned)src >= (unsigned)N_NODES) return;
    if ((unsigned)dst >= (unsigned)N_NODES) return;
    float norm = rsqrtf(g_deg[src]) * rsqrtf(g_deg[dst]);
    float2 v = ((const float2*)(g_h + src * D))[lane];
    atomicAdd(&g_agg[dst * D + lane * 2],     norm * v.x);
    atomicAdd(&g_agg[dst * D + lane * 2 + 1], norm * v.y);
}

// ------- bias + relu + bf16 hi/lo split-pack: A2=[hi|lo|hi], B2=[hi|hi|lo] -------
__global__ void k_bias_relu_pack() {
    const float* __restrict__ b = gp_b;
    int idx = blockIdx.x * blockDim.x + threadIdx.x;
    if (idx >= N_NODES * D) return;
    int row = idx >> 6, col = idx & 63;
    float v = g_agg[idx] + b[col];
    v = v > 0.0f ? v : 0.0f;
    __nv_bfloat16 hi = __float2bfloat16(v);
    __nv_bfloat16 lo = __float2bfloat16(v - __bfloat162float(hi));
    __nv_bfloat16* a2 = g_A2 + row * KC;
    __nv_bfloat16* b2 = g_B2 + row * KC;
    a2[col] = hi; a2[col + 64] = lo; a2[col + 128] = hi;
    b2[col] = hi; b2[col + 64] = hi; b2[col + 128] = lo;
}

// ---------------- C = A2 @ B2^T via mma.sync bf16, 128x128 tile, K=192 --------
// smem: row-major 128 x 192 bf16 per tile (384 B/row = 24 x 16B chunks),
// chunk swizzle within 8-chunk groups: c' = (c & 24) | ((c & 7) ^ (row & 7)).
// ldmatrix.x4 then reads 8 rows at the same k-chunk conflict-free.
#define ROW_BYTES (KC * 2)                  // 384
#define TILE_BYTES (128 * ROW_BYTES)        // 49152
#define SMEM_TOTAL (2 * TILE_BYTES)         // 98304

__device__ __forceinline__ uint32_t sw_off(int row, int chunk) {
    return (uint32_t)(row * ROW_BYTES + (((chunk & 24) | ((chunk & 7) ^ (row & 7))) << 4));
}

#define LDSM_X4(r0, r1, r2, r3, a) \
    asm volatile("ldmatrix.sync.aligned.m8n8.x4.shared.b16 {%0,%1,%2,%3}, [%4];" \
        : "=r"(r0), "=r"(r1), "=r"(r2), "=r"(r3) : "r"(a))

#define MMA_16816(d, a, b) \
    asm volatile("mma.sync.aligned.m16n8k16.row.col.f32.bf16.bf16.f32 " \
        "{%0,%1,%2,%3}, {%4,%5,%6,%7}, {%8,%9}, {%0,%1,%2,%3};" \
        : "+f"((d)[0]), "+f"((d)[1]), "+f"((d)[2]), "+f"((d)[3]) \
        : "r"((a)[0]), "r"((a)[1]), "r"((a)[2]), "r"((a)[3]), "r"((b)[0]), "r"((b)[1]))

__global__ void __launch_bounds__(256, 2) k_gemm_mma(float* __restrict__ C) {
    extern __shared__ char smem[];
    char* sA = smem;
    char* sB = smem + TILE_BYTES;
    uint32_t sA_u = smem_u32(sA);
    uint32_t sB_u = smem_u32(sB);

    int tid = threadIdx.x;
    int wid = tid >> 5, lane = tid & 31;
    int bi = blockIdx.y, bj = blockIdx.x;
    int warp_m = wid >> 1;         // 0..3 -> 32-row slice
    int warp_n = wid & 1;          // 0..1 -> 64-col slice

    // ---- load tiles: 3072 uint4 each, 12 iters x 256 threads ----
    const uint4* gA = (const uint4*)(g_A2 + bi * 128 * KC);
    const uint4* gB = (const uint4*)(g_B2 + bj * 128 * KC);
#pragma unroll
    for (int it = 0; it < 12; it++) {
        int q = it * 256 + tid;            // 0..3071
        int row = q / 24, chunk = q % 24;
        uint32_t off = sw_off(row, chunk);
        *(uint4*)(sA + off) = gA[q];
        *(uint4*)(sB + off) = gB[q];
    }
    __syncthreads();

    // ---- per-thread ldmatrix row addressing ----
    // A (x4): lanes 0-7 rows r0..7 chunk c; 8-15 rows r8..15 chunk c; 16-23 rows r0..7
    //         chunk c+1; 24-31 rows r8..15 chunk c+1.
    int a_row_in16 = (lane & 7) | (lane & 8);      // (lane&7) + ((lane>>3)&1)*8
    int a_csub = lane >> 4;                        // 0 or 1
    // B (x4): lanes 0-7 rows n0..7 chunk c; 8-15 rows n0..7 chunk c+1;
    //         16-23 rows n8..15 chunk c; 24-31 rows n8..15 chunk c+1.
    int b_row_in16 = (lane & 7) | ((lane >> 1) & 8);
    int b_csub = (lane >> 3) & 1;

    float acc[2][8][4];
#pragma unroll
    for (int mi = 0; mi < 2; mi++)
#pragma unroll
        for (int ni = 0; ni < 8; ni++)
#pragma unroll
            for (int v = 0; v < 4; v++) acc[mi][ni][v] = 0.0f;

#pragma unroll
    for (int s = 0; s < 12; s++) {
        int kc = s * 2;   // base 16B chunk of this k16 step

        uint32_t a[2][4];
#pragma unroll
        for (int mi = 0; mi < 2; mi++) {
            int row = warp_m * 32 + mi * 16 + a_row_in16;
            uint32_t addr = sA_u + sw_off(row, kc + a_csub);
            LDSM_X4(a[mi][0], a[mi][1], a[mi][2], a[mi][3], addr);
        }

        uint32_t b[4][4];
#pragma unroll
        for (int nt = 0; nt < 4; nt++) {
            int row = warp_n * 64 + nt * 16 + b_row_in16;
            uint32_t addr = sB_u + sw_off(row, kc + b_csub);
            LDSM_X4(b[nt][0], b[nt][1], b[nt][2], b[nt][3], addr);
        }

#pragma unroll
        for (int mi = 0; mi < 2; mi++)
#pragma unroll
            for (int ni = 0; ni < 8; ni++) {
                uint32_t bb[2];
                bb[0] = b[ni >> 1][(ni & 1) * 2];
                bb[1] = b[ni >> 1][(ni & 1) * 2 + 1];
                MMA_16816(acc[mi][ni], a[mi], bb);
            }
    }

    // ---- epilogue ----
    int gr = lane >> 2, gc = (lane & 3) * 2;
#pragma unroll
    for (int mi = 0; mi < 2; mi++) {
        int row0 = bi * 128 + warp_m * 32 + mi * 16 + gr;
#pragma unroll
        for (int ni = 0; ni < 8; ni++) {
            int col = bj * 128 + warp_n * 64 + ni * 8 + gc;
            float* p0 = C + (long long)row0 * NT + col;
            float* p1 = p0 + 8LL * NT;
            *(float2*)p0 = make_float2(acc[mi][ni][0], acc[mi][ni][1]);
            *(float2*)p1 = make_float2(acc[mi][ni][2], acc[mi][ni][3]);
        }
    }
}

extern "C" void kernel_launch(void* const* d_in, const int* in_sizes, int n_in,
                              void* d_out, int out_size) {
    float* out = (float*)d_out;

    const void* p0 = n_in > 0 ? d_in[0] : nullptr;
    const void* p1 = n_in > 1 ? d_in[1] : nullptr;
    const void* p2 = n_in > 2 ? d_in[2] : nullptr;
    const void* p3 = n_in > 3 ? d_in[3] : nullptr;
    int s0 = n_in > 0 ? in_sizes[0] : 0;
    int s1 = n_in > 1 ? in_sizes[1] : 0;
    int s2 = n_in > 2 ? in_sizes[2] : 0;
    int s3 = n_in > 3 ? in_sizes[3] : 0;

    int Emax = 0;
    for (int i = 0; i < n_in && i < 4; i++) {
        int s = in_sizes[i];
        if (s != D && s != D * D && s / 2 > Emax) Emax = s / 2;
    }

    static bool attr_set = false;
    if (!attr_set) {
        cudaFuncSetAttribute(k_gemm_mma, cudaFuncAttributeMaxDynamicSharedMemorySize, SMEM_TOTAL);
        attr_set = true;
    }

    k_classify_deginit<<<(N_NODES + 255) / 256, 256>>>(p0, p1, p2, p3, s0, s1, s2, s3);
    k_deg_count<<<(Emax + 255) / 256, 256>>>(Emax);
    k_xw<<<N_NODES / 4, 256>>>();
    k_agg_init<<<(N_NODES * D + 255) / 256, 256>>>();
    k_scatter<<<(Emax + 7) / 8, 256>>>(Emax);
    k_bias_relu_pack<<<(N_NODES * D + 255) / 256, 256>>>();

    dim3 grid(NT / 128, NT / 128);
    k_gemm_mma<<<grid, 256, SMEM_TOTAL>>>(out);
}

// round 6
// speedup vs baseline: 1.6533x; 1.0228x over previous
#include <cuda_runtime.h>
#include <cuda_bf16.h>
#include <math.h>
#include <stdint.h>

#define N_NODES 8192
#define D 64
#define NT 8192
#define KC 192            // packed K: [hi | lo | hi] / [hi | hi | lo]

// ---------------- scratch (no allocations allowed) ----------------
__device__ float g_deg[N_NODES];
__device__ float g_h[N_NODES * D];     // x @ W
__device__ float g_agg[N_NODES * D];   // aggregated
__device__ __nv_bfloat16 g_A2[N_NODES * KC];
__device__ __nv_bfloat16 g_B2[N_NODES * KC];

// Resolved input pointers (metadata order/dtype untrusted -> classify at runtime)
__device__ const float* gp_x;
__device__ const void*  gp_ei;
__device__ const float* gp_W;
__device__ const float* gp_b;
__device__ int          g_E;
__device__ int          g_ei32;   // 1 if edge indices are int32, 0 if int64

__device__ __forceinline__ int fetch_idx(int i, int ei32) {
    if (ei32) return ((const int*)gp_ei)[i];
    return (int)((const long long*)gp_ei)[i];
}

__device__ __forceinline__ uint32_t smem_u32(const void* p) {
    uint32_t a;
    asm("{ .reg .u64 t; cvta.to.shared.u64 t, %1; cvt.u32.u64 %0, t; }" : "=r"(a) : "l"(p));
    return a;
}

// ---------------- classify (thread 0) + deg init (all) ----------------
__device__ bool range_ok_i64(const long long* p, int n) {
    int stride = n / 64; if (stride < 1) stride = 1;
    for (int k = 0; k < 64; k++) {
        long long v = p[(long long)k * stride];
        if (v < 0 || v >= N_NODES) return false;
    }
    return true;
}
__device__ bool range_ok_i32(const int* p, int n) {
    int stride = n / 64; if (stride < 1) stride = 1;
    for (int k = 0; k < 64; k++) {
        int v = p[k * stride];
        if (v < 0 || v >= N_NODES) return false;
    }
    return true;
}

__global__ void k_classify_deginit(const void* p0, const void* p1, const void* p2, const void* p3,
                                   int s0, int s1, int s2, int s3) {
    int i = blockIdx.x * blockDim.x + threadIdx.x;
    if (i < N_NODES) g_deg[i] = 1.0f;  // self-loop
    if (i != 0) return;

    const void* ps[4] = {p0, p1, p2, p3};
    int ss[4] = {s0, s1, s2, s3};
    int big[2]; int nb = 0;
    for (int j = 0; j < 4; j++) {
        if (ss[j] == D) gp_b = (const float*)ps[j];
        else if (ss[j] == D * D) gp_W = (const float*)ps[j];
        else if (nb < 2) big[nb++] = j;
    }
    for (int c = 0; c < 2; c++) {
        const void* cand = ps[big[c]];
        int n = ss[big[c]];
        const void* other = ps[big[1 - c]];
        if (range_ok_i64((const long long*)cand, n)) {
            gp_ei = cand; g_ei32 = 0; g_E = n / 2; gp_x = (const float*)other; return;
        }
        if (range_ok_i32((const int*)cand, n)) {
            gp_ei = cand; g_ei32 = 1; g_E = n / 2; gp_x = (const float*)other; return;
        }
    }
    gp_ei = ps[big[1]]; g_ei32 = 1; g_E = ss[big[1]] / 2;
    gp_x = (const float*)ps[big[0]];
}

__global__ void k_deg_count(int Emax) {
    int e = blockIdx.x * blockDim.x + threadIdx.x;
    int E = g_E, ei32 = g_ei32;
    if (e < E && e < Emax) {
        int dst = fetch_idx(E + e, ei32);
        if ((unsigned)dst < (unsigned)N_NODES) atomicAdd(&g_deg[dst], 1.0f);
    }
}

// -------- h = x @ W, fused with agg init (g_agg = h/deg, self-loop term) --------
__global__ void k_xw_agg() {
    __shared__ float sW[D * D];
    const float* __restrict__ x = gp_x;
    const float* __restrict__ W = gp_W;
    int tid = threadIdx.x;
    for (int i = tid; i < D * D; i += 256) sW[i] = W[i];
    __syncthreads();
    int row = blockIdx.x * 4 + (tid >> 6);
    int col = tid & 63;
    const float* xr = x + row * D;
    float acc = 0.0f;
#pragma unroll
    for (int k = 0; k < D; k++) acc += xr[k] * sW[k * D + col];
    g_h[row * D + col] = acc;
    float di = rsqrtf(g_deg[row]);
    g_agg[row * D + col] = di * di * acc;
}

// ---------------- edge scatter: warp per edge ----------------
__global__ void k_scatter(int Emax) {
    int gw = (blockIdx.x * blockDim.x + threadIdx.x) >> 5;
    int lane = threadIdx.x & 31;
    int E = g_E, ei32 = g_ei32;
    if (gw >= E || gw >= Emax) return;
    int src = fetch_idx(gw, ei32);
    int dst = fetch_idx(E + gw, ei32);
    if ((unsigned)src >= (unsigned)N_NODES) return;
    if ((unsigned)dst >= (unsigned)N_NODES) return;
    float norm = rsqrtf(g_deg[src]) * rsqrtf(g_deg[dst]);
    float2 v = ((const float2*)(g_h + src * D))[lane];
    atomicAdd(&g_agg[dst * D + lane * 2],     norm * v.x);
    atomicAdd(&g_agg[dst * D + lane * 2 + 1], norm * v.y);
}

// ------- bias + relu + bf16 hi/lo split-pack: A2=[hi|lo|hi], B2=[hi|hi|lo] -------
__global__ void k_bias_relu_pack() {
    const float* __restrict__ b = gp_b;
    int idx = blockIdx.x * blockDim.x + threadIdx.x;
    if (idx >= N_NODES * D) return;
    int row = idx >> 6, col = idx & 63;
    float v = g_agg[idx] + b[col];
    v = v > 0.0f ? v : 0.0f;
    __nv_bfloat16 hi = __float2bfloat16(v);
    __nv_bfloat16 lo = __float2bfloat16(v - __bfloat162float(hi));
    __nv_bfloat16* a2 = g_A2 + row * KC;
    __nv_bfloat16* b2 = g_B2 + row * KC;
    a2[col] = hi; a2[col + 64] = lo; a2[col + 128] = hi;
    b2[col] = hi; b2[col + 64] = hi; b2[col + 128] = lo;
}

// ------- C = A2 @ B2^T via mma.sync bf16, symmetric: upper-tri tiles only -------
// smem: row-major 128 x 192 bf16 per tile (384 B/row = 24 x 16B chunks),
// chunk swizzle within 8-chunk groups: c' = (c & 24) | ((c & 7) ^ (row & 7)).
#define ROW_BYTES (KC * 2)                  // 384
#define TILE_BYTES (128 * ROW_BYTES)        // 49152
#define SMEM_TOTAL (2 * TILE_BYTES)         // 98304
#define TSTRIDE 132                          // fp32 transpose stage stride

__device__ __forceinline__ uint32_t sw_off(int row, int chunk) {
    return (uint32_t)(row * ROW_BYTES + (((chunk & 24) | ((chunk & 7) ^ (row & 7))) << 4));
}

#define LDSM_X4(r0, r1, r2, r3, a) \
    asm volatile("ldmatrix.sync.aligned.m8n8.x4.shared.b16 {%0,%1,%2,%3}, [%4];" \
        : "=r"(r0), "=r"(r1), "=r"(r2), "=r"(r3) : "r"(a))

#define MMA_16816(d, a, b) \
    asm volatile("mma.sync.aligned.m16n8k16.row.col.f32.bf16.bf16.f32 " \
        "{%0,%1,%2,%3}, {%4,%5,%6,%7}, {%8,%9}, {%0,%1,%2,%3};" \
        : "+f"((d)[0]), "+f"((d)[1]), "+f"((d)[2]), "+f"((d)[3]) \
        : "r"((a)[0]), "r"((a)[1]), "r"((a)[2]), "r"((a)[3]), "r"((b)[0]), "r"((b)[1]))

#define CP_ASYNC_16(smem_addr, gptr) \
    asm volatile("cp.async.cg.shared.global [%0], [%1], 16;" :: "r"(smem_addr), "l"(gptr) : "memory")

__global__ void __launch_bounds__(256, 2) k_gemm_mma(float* __restrict__ C) {
    int bi = blockIdx.y, bj = blockIdx.x;
    if (bj < bi) return;   // symmetric: compute upper triangle only

    extern __shared__ char smem[];
    char* sA = smem;
    char* sB = smem + TILE_BYTES;
    uint32_t sA_u = smem_u32(sA);
    uint32_t sB_u = smem_u32(sB);

    int tid = threadIdx.x;
    int wid = tid >> 5, lane = tid & 31;
    int warp_m = wid >> 1;         // 0..3 -> 32-row slice
    int warp_n = wid & 1;          // 0..1 -> 64-col slice

    // ---- cp.async tile loads: 3072 16B chunks each ----
    const char* gA = (const char*)(g_A2 + bi * 128 * KC);
    const char* gB = (const char*)(g_B2 + bj * 128 * KC);
#pragma unroll
    for (int it = 0; it < 12; it++) {
        int q = it * 256 + tid;            // 0..3071
        int row = q / 24, chunk = q % 24;
        uint32_t off = sw_off(row, chunk);
        CP_ASYNC_16(sA_u + off, gA + q * 16);
        CP_ASYNC_16(sB_u + off, gB + q * 16);
    }
    asm volatile("cp.async.commit_group;" ::: "memory");
    asm volatile("cp.async.wait_group 0;" ::: "memory");
    __syncthreads();

    // ---- per-thread ldmatrix row addressing ----
    int a_row_in16 = (lane & 7) | (lane & 8);
    int a_csub = lane >> 4;
    int b_row_in16 = (lane & 7) | ((lane >> 1) & 8);
    int b_csub = (lane >> 3) & 1;

    float acc[2][8][4];
#pragma unroll
    for (int mi = 0; mi < 2; mi++)
#pragma unroll
        for (int ni = 0; ni < 8; ni++)
#pragma unroll
            for (int v = 0; v < 4; v++) acc[mi][ni][v] = 0.0f;

#pragma unroll
    for (int s = 0; s < 12; s++) {
        int kc = s * 2;

        uint32_t a[2][4];
#pragma unroll
        for (int mi = 0; mi < 2; mi++) {
            int row = warp_m * 32 + mi * 16 + a_row_in16;
            uint32_t addr = sA_u + sw_off(row, kc + a_csub);
            LDSM_X4(a[mi][0], a[mi][1], a[mi][2], a[mi][3], addr);
        }

        uint32_t b[4][4];
#pragma unroll
        for (int nt = 0; nt < 4; nt++) {
            int row = warp_n * 64 + nt * 16 + b_row_in16;
            uint32_t addr = sB_u + sw_off(row, kc + b_csub);
            LDSM_X4(b[nt][0], b[nt][1], b[nt][2], b[nt][3], addr);
        }

#pragma unroll
        for (int mi = 0; mi < 2; mi++)
#pragma unroll
            for (int ni = 0; ni < 8; ni++) {
                uint32_t bb[2];
                bb[0] = b[ni >> 1][(ni & 1) * 2];
                bb[1] = b[ni >> 1][(ni & 1) * 2 + 1];
                MMA_16816(acc[mi][ni], a[mi], bb);
            }
    }

    // ---- epilogue 1: direct coalesced store of C[bi, bj] ----
    int gr = lane >> 2, gc = (lane & 3) * 2;
#pragma unroll
    for (int mi = 0; mi < 2; mi++) {
        int row0 = bi * 128 + warp_m * 32 + mi * 16 + gr;
#pragma unroll
        for (int ni = 0; ni < 8; ni++) {
            int col = bj * 128 + warp_n * 64 + ni * 8 + gc;
            float* p0 = C + (long long)row0 * NT + col;
            float* p1 = p0 + 8LL * NT;
            *(float2*)p0 = make_float2(acc[mi][ni][0], acc[mi][ni][1]);
            *(float2*)p1 = make_float2(acc[mi][ni][2], acc[mi][ni][3]);
        }
    }

    // ---- epilogue 2: transposed store of C[bj, bi] via smem staging ----
    if (bi == bj) return;
    __syncthreads();   // done reading sA/sB
    float* sT = (float*)smem;   // 128 x TSTRIDE floats = 67584 B < 96 KB
#pragma unroll
    for (int mi = 0; mi < 2; mi++) {
        int lr = warp_m * 32 + mi * 16 + gr;   // local row in (bi,bj) tile
#pragma unroll
        for (int ni = 0; ni < 8; ni++) {
            int lc = warp_n * 64 + ni * 8 + gc;  // local col
            sT[lc * TSTRIDE + lr]           = acc[mi][ni][0];
            sT[(lc + 1) * TSTRIDE + lr]     = acc[mi][ni][1];
            sT[lc * TSTRIDE + lr + 8]       = acc[mi][ni][2];
            sT[(lc + 1) * TSTRIDE + lr + 8] = acc[mi][ni][3];
        }
    }
    __syncthreads();
    // write transposed tile: rows bj*128.., cols bi*128..  (coalesced)
    int half = tid >> 7;            // 0/1 -> col halves
    int r = tid & 127;              // transposed-tile row
    const float* srow = sT + r * TSTRIDE + half * 64;
    float* drow = C + (long long)(bj * 128 + r) * NT + bi * 128 + half * 64;
#pragma unroll
    for (int k = 0; k < 16; k++) {
        float4 v = *(const float4*)(srow + k * 4);
        *(float4*)(drow + k * 4) = v;
    }
}

extern "C" void kernel_launch(void* const* d_in, const int* in_sizes, int n_in,
                              void* d_out, int out_size) {
    float* out = (float*)d_out;

    const void* p0 = n_in > 0 ? d_in[0] : nullptr;
    const void* p1 = n_in > 1 ? d_in[1] : nullptr;
    const void* p2 = n_in > 2 ? d_in[2] : nullptr;
    const void* p3 = n_in > 3 ? d_in[3] : nullptr;
    int s0 = n_in > 0 ? in_sizes[0] : 0;
    int s1 = n_in > 1 ? in_sizes[1] : 0;
    int s2 = n_in > 2 ? in_sizes[2] : 0;
    int s3 = n_in > 3 ? in_sizes[3] : 0;

    int Emax = 0;
    for (int i = 0; i < n_in && i < 4; i++) {
        int s = in_sizes[i];
        if (s != D && s != D * D && s / 2 > Emax) Emax = s / 2;
    }

    static bool attr_set = false;
    if (!attr_set) {
        cudaFuncSetAttribute(k_gemm_mma, cudaFuncAttributeMaxDynamicSharedMemorySize, SMEM_TOTAL);
        attr_set = true;
    }

    k_classify_deginit<<<(N_NODES + 255) / 256, 256>>>(p0, p1, p2, p3, s0, s1, s2, s3);
    k_deg_count<<<(Emax + 255) / 256, 256>>>(Emax);
    k_xw_agg<<<N_NODES / 4, 256>>>();
    k_scatter<<<(Emax + 7) / 8, 256>>>(Emax);
    k_bias_relu_pack<<<(N_NODES * D + 255) / 256, 256>>>();

    dim3 grid(NT / 128, NT / 128);
    k_gemm_mma<<<grid, 256, SMEM_TOTAL>>>(out);
}